// round 4
// baseline (speedup 1.0000x reference)
#include <cuda_runtime.h>

// Fixed problem shape (from reference): N = 100,000 nodes.
#define MAX_NODES 100000

// Combined scratch table: [0, N) = out-degree (by src), [N, 2N) = in-degree
// (by dst). Later overwritten in-place with rsqrt(deg).
__device__ float g_norm[2 * MAX_NODES];

// ---------------------------------------------------------------------------
// Kernel 1: zero the accumulators, float4-vectorized. Device globals persist
// across graph replays, so they MUST be re-zeroed on every launch.
// ---------------------------------------------------------------------------
__global__ void zero_deg_kernel() {
    int i = blockIdx.x * blockDim.x + threadIdx.x;
    if (i < (2 * MAX_NODES) / 4) {
        ((float4*)g_norm)[i] = make_float4(0.f, 0.f, 0.f, 0.f);
    }
}

// ---------------------------------------------------------------------------
// Kernel 2: scatter edge weights into out-degree (by src) and in-degree (by
// dst). 8 edges per thread (two float4/int4 groups), all streaming loads
// front-batched, then 16 consumer-free REDG.ADD back-to-back -> max
// outstanding atomics per warp. Bound by spread-addr REDG rate.
// ---------------------------------------------------------------------------
__global__ void __launch_bounds__(256)
scatter_deg_kernel(const float4* __restrict__ w4,
                   const int4*   __restrict__ s4,
                   const int4*   __restrict__ d4,
                   int n4) {
    int t = blockIdx.x * blockDim.x + threadIdx.x;
    int i0 = 2 * t;
    int i1 = 2 * t + 1;
    if (i0 >= n4) return;
    bool has1 = (i1 < n4);
    int i1c = has1 ? i1 : i0;  // clamp: duplicate-load, atomics predicated off

    // Front-batch all 6 streaming loads (deep MLP, no consumers until ready).
    float4 wv0 = w4[i0];
    int4   sv0 = s4[i0];
    int4   dv0 = d4[i0];
    float4 wv1 = w4[i1c];
    int4   sv1 = s4[i1c];
    int4   dv1 = d4[i1c];

    atomicAdd(&g_norm[sv0.x], wv0.x);
    atomicAdd(&g_norm[sv0.y], wv0.y);
    atomicAdd(&g_norm[sv0.z], wv0.z);
    atomicAdd(&g_norm[sv0.w], wv0.w);
    atomicAdd(&g_norm[MAX_NODES + dv0.x], wv0.x);
    atomicAdd(&g_norm[MAX_NODES + dv0.y], wv0.y);
    atomicAdd(&g_norm[MAX_NODES + dv0.z], wv0.z);
    atomicAdd(&g_norm[MAX_NODES + dv0.w], wv0.w);
    if (has1) {
        atomicAdd(&g_norm[sv1.x], wv1.x);
        atomicAdd(&g_norm[sv1.y], wv1.y);
        atomicAdd(&g_norm[sv1.z], wv1.z);
        atomicAdd(&g_norm[sv1.w], wv1.w);
        atomicAdd(&g_norm[MAX_NODES + dv1.x], wv1.x);
        atomicAdd(&g_norm[MAX_NODES + dv1.y], wv1.y);
        atomicAdd(&g_norm[MAX_NODES + dv1.z], wv1.z);
        atomicAdd(&g_norm[MAX_NODES + dv1.w], wv1.w);
    }
}

// Scalar tail for generality (launched only when E % 4 != 0).
__global__ void scatter_tail_kernel(const float* __restrict__ w,
                                    const int*   __restrict__ s,
                                    const int*   __restrict__ d,
                                    int start, int E) {
    int i = start + blockIdx.x * blockDim.x + threadIdx.x;
    if (i < E) {
        float wv = w[i];
        atomicAdd(&g_norm[s[i]], wv);
        atomicAdd(&g_norm[MAX_NODES + d[i]], wv);
    }
}

// ---------------------------------------------------------------------------
// Kernel 3: per-node rsqrt, in place, float4-vectorized over the combined
// table. deg==0 -> +inf, but such nodes never appear on the corresponding
// side of any edge, so the inf is never gathered.
// ---------------------------------------------------------------------------
__global__ void rsqrt_deg_kernel() {
    int i = blockIdx.x * blockDim.x + threadIdx.x;
    if (i < (2 * MAX_NODES) / 4) {
        float4 v = ((float4*)g_norm)[i];
        v.x = rsqrtf(v.x);
        v.y = rsqrtf(v.y);
        v.z = rsqrtf(v.z);
        v.w = rsqrtf(v.w);
        ((float4*)g_norm)[i] = v;
    }
}

// ---------------------------------------------------------------------------
// Kernel 4: per-edge gather-multiply. EXACT R3 winner (174us): 4 edges per
// thread, front-batched gathers; L1tex wavefront-bound at ~90% of peak.
// ---------------------------------------------------------------------------
__global__ void gather_mul_kernel(const float4* __restrict__ w4,
                                  const int4*   __restrict__ s4,
                                  const int4*   __restrict__ d4,
                                  float4* __restrict__ out4,
                                  int n4) {
    int tid = blockIdx.x * blockDim.x + threadIdx.x;
    if (tid >= n4) return;
    float4 wv = w4[tid];
    int4   sv = s4[tid];
    int4   dv = d4[tid];
    // Front-batch all 8 random gathers for deep MLP.
    float sx = g_norm[sv.x], sy = g_norm[sv.y];
    float sz = g_norm[sv.z], sw = g_norm[sv.w];
    float dx = g_norm[MAX_NODES + dv.x], dy = g_norm[MAX_NODES + dv.y];
    float dz = g_norm[MAX_NODES + dv.z], dw = g_norm[MAX_NODES + dv.w];
    float4 r;
    r.x = sx * dx * wv.x;
    r.y = sy * dy * wv.y;
    r.z = sz * dz * wv.z;
    r.w = sw * dw * wv.w;
    out4[tid] = r;
}

// Scalar tail for generality (launched only when E % 4 != 0).
__global__ void gather_tail_kernel(const float* __restrict__ w,
                                   const int*   __restrict__ s,
                                   const int*   __restrict__ d,
                                   float* __restrict__ out,
                                   int start, int E) {
    int i = start + blockIdx.x * blockDim.x + threadIdx.x;
    if (i < E) {
        out[i] = g_norm[s[i]] * g_norm[MAX_NODES + d[i]] * w[i];
    }
}

extern "C" void kernel_launch(void* const* d_in, const int* in_sizes, int n_in,
                              void* d_out, int out_size) {
    const float* w   = (const float*)d_in[0];
    const int*   src = (const int*)d_in[1];
    const int*   dst = (const int*)d_in[2];
    float* out = (float*)d_out;

    int E    = in_sizes[0];
    int n4   = E / 4;
    int tail = E - 4 * n4;

    const int TPB = 256;
    const int NV4 = (2 * MAX_NODES) / 4;  // 100,000 float4s

    zero_deg_kernel<<<(NV4 + TPB - 1) / TPB, TPB>>>();

    int nthreads_sc = (n4 + 1) / 2;  // 8 edges per thread
    scatter_deg_kernel<<<(nthreads_sc + TPB - 1) / TPB, TPB>>>(
        (const float4*)w, (const int4*)src, (const int4*)dst, n4);
    if (tail > 0) {
        scatter_tail_kernel<<<1, TPB>>>(w, src, dst, 4 * n4, E);
    }

    rsqrt_deg_kernel<<<(NV4 + TPB - 1) / TPB, TPB>>>();

    gather_mul_kernel<<<(n4 + TPB - 1) / TPB, TPB>>>(
        (const float4*)w, (const int4*)src, (const int4*)dst,
        (float4*)out, n4);
    if (tail > 0) {
        gather_tail_kernel<<<1, TPB>>>(w, src, dst, out, 4 * n4, E);
    }
}

// round 5
// speedup vs baseline: 1.0122x; 1.0122x over previous
#include <cuda_runtime.h>

// Fixed problem shape (from reference): N = 100,000 nodes.
#define MAX_NODES 100000

// Combined scratch table: [0, N) = out-degree (by src), [N, 2N) = in-degree
// (by dst). Later overwritten in-place with rsqrt(deg).
__device__ float g_norm[2 * MAX_NODES];

// ---------------------------------------------------------------------------
// Kernel 1: zero the accumulators, float4-vectorized. Device globals persist
// across graph replays, so they MUST be re-zeroed on every launch.
// ---------------------------------------------------------------------------
__global__ void zero_deg_kernel() {
    int i = blockIdx.x * blockDim.x + threadIdx.x;
    if (i < (2 * MAX_NODES) / 4) {
        ((float4*)g_norm)[i] = make_float4(0.f, 0.f, 0.f, 0.f);
    }
}

// ---------------------------------------------------------------------------
// Kernel 2: scatter edge weights into out-degree (by src) and in-degree (by
// dst). 4 edges per thread via float4/int4 loads (measured best: 8-edge
// unroll regressed — phase is LTS-atomic-throughput bound, not issue bound).
// atomicAdd with unused return -> REDG (no round trip).
// ---------------------------------------------------------------------------
__global__ void __launch_bounds__(256)
scatter_deg_kernel(const float4* __restrict__ w4,
                   const int4*   __restrict__ s4,
                   const int4*   __restrict__ d4,
                   int n4) {
    int tid = blockIdx.x * blockDim.x + threadIdx.x;
    if (tid >= n4) return;
    int4   sv = s4[tid];
    int4   dv = d4[tid];
    float4 wv = w4[tid];
    atomicAdd(&g_norm[sv.x], wv.x);
    atomicAdd(&g_norm[sv.y], wv.y);
    atomicAdd(&g_norm[sv.z], wv.z);
    atomicAdd(&g_norm[sv.w], wv.w);
    atomicAdd(&g_norm[MAX_NODES + dv.x], wv.x);
    atomicAdd(&g_norm[MAX_NODES + dv.y], wv.y);
    atomicAdd(&g_norm[MAX_NODES + dv.z], wv.z);
    atomicAdd(&g_norm[MAX_NODES + dv.w], wv.w);
}

// Scalar tail for generality (launched only when E % 4 != 0).
__global__ void scatter_tail_kernel(const float* __restrict__ w,
                                    const int*   __restrict__ s,
                                    const int*   __restrict__ d,
                                    int start, int E) {
    int i = start + blockIdx.x * blockDim.x + threadIdx.x;
    if (i < E) {
        float wv = w[i];
        atomicAdd(&g_norm[s[i]], wv);
        atomicAdd(&g_norm[MAX_NODES + d[i]], wv);
    }
}

// ---------------------------------------------------------------------------
// Kernel 3: per-node rsqrt, in place, float4-vectorized over the combined
// table. deg==0 -> +inf, but such nodes never appear on the corresponding
// side of any edge, so the inf is never gathered.
// ---------------------------------------------------------------------------
__global__ void rsqrt_deg_kernel() {
    int i = blockIdx.x * blockDim.x + threadIdx.x;
    if (i < (2 * MAX_NODES) / 4) {
        float4 v = ((float4*)g_norm)[i];
        v.x = rsqrtf(v.x);
        v.y = rsqrtf(v.y);
        v.z = rsqrtf(v.z);
        v.w = rsqrtf(v.w);
        ((float4*)g_norm)[i] = v;
    }
}

// ---------------------------------------------------------------------------
// Kernel 4: per-edge gather-multiply. R3 winner (174us): 4 edges per thread,
// indices loaded first so the 8 dependent random gathers issue ASAP;
// L1tex-wavefront bound at ~90% of peak (architectural floor).
// ---------------------------------------------------------------------------
__global__ void __launch_bounds__(256)
gather_mul_kernel(const float4* __restrict__ w4,
                  const int4*   __restrict__ s4,
                  const int4*   __restrict__ d4,
                  float4* __restrict__ out4,
                  int n4) {
    int tid = blockIdx.x * blockDim.x + threadIdx.x;
    if (tid >= n4) return;
    int4   sv = s4[tid];
    int4   dv = d4[tid];
    float4 wv = w4[tid];
    // Front-batch all 8 random gathers for deep MLP.
    float sx = g_norm[sv.x], sy = g_norm[sv.y];
    float sz = g_norm[sv.z], sw = g_norm[sv.w];
    float dx = g_norm[MAX_NODES + dv.x], dy = g_norm[MAX_NODES + dv.y];
    float dz = g_norm[MAX_NODES + dv.z], dw = g_norm[MAX_NODES + dv.w];
    float4 r;
    r.x = sx * dx * wv.x;
    r.y = sy * dy * wv.y;
    r.z = sz * dz * wv.z;
    r.w = sw * dw * wv.w;
    out4[tid] = r;
}

// Scalar tail for generality (launched only when E % 4 != 0).
__global__ void gather_tail_kernel(const float* __restrict__ w,
                                   const int*   __restrict__ s,
                                   const int*   __restrict__ d,
                                   float* __restrict__ out,
                                   int start, int E) {
    int i = start + blockIdx.x * blockDim.x + threadIdx.x;
    if (i < E) {
        out[i] = g_norm[s[i]] * g_norm[MAX_NODES + d[i]] * w[i];
    }
}

extern "C" void kernel_launch(void* const* d_in, const int* in_sizes, int n_in,
                              void* d_out, int out_size) {
    const float* w   = (const float*)d_in[0];
    const int*   src = (const int*)d_in[1];
    const int*   dst = (const int*)d_in[2];
    float* out = (float*)d_out;

    int E    = in_sizes[0];
    int n4   = E / 4;
    int tail = E - 4 * n4;

    const int TPB = 256;
    const int NV4 = (2 * MAX_NODES) / 4;  // 100,000 float4s

    zero_deg_kernel<<<(NV4 + TPB - 1) / TPB, TPB>>>();

    scatter_deg_kernel<<<(n4 + TPB - 1) / TPB, TPB>>>(
        (const float4*)w, (const int4*)src, (const int4*)dst, n4);
    if (tail > 0) {
        scatter_tail_kernel<<<1, TPB>>>(w, src, dst, 4 * n4, E);
    }

    rsqrt_deg_kernel<<<(NV4 + TPB - 1) / TPB, TPB>>>();

    gather_mul_kernel<<<(n4 + TPB - 1) / TPB, TPB>>>(
        (const float4*)w, (const int4*)src, (const int4*)dst,
        (float4*)out, n4);
    if (tail > 0) {
        gather_tail_kernel<<<1, TPB>>>(w, src, dst, out, 4 * n4, E);
    }
}

// round 6
// speedup vs baseline: 1.0127x; 1.0004x over previous
#include <cuda_runtime.h>

// Fixed problem shape (from reference): N = 100,000 nodes.
#define MAX_NODES 100000

// Combined scratch table: [0, N) = out-degree (by src), [N, 2N) = in-degree
// (by dst). Later overwritten in-place with rsqrt(deg).
__device__ float g_norm[2 * MAX_NODES];

// ---------------------------------------------------------------------------
// Kernel 1: zero the accumulators, float4-vectorized. Device globals persist
// across graph replays, so they MUST be re-zeroed on every launch.
// ---------------------------------------------------------------------------
__global__ void zero_deg_kernel() {
    int i = blockIdx.x * blockDim.x + threadIdx.x;
    if (i < (2 * MAX_NODES) / 4) {
        ((float4*)g_norm)[i] = make_float4(0.f, 0.f, 0.f, 0.f);
    }
}

// ---------------------------------------------------------------------------
// Kernel 2: scatter edge weights into out-degree (by src) and in-degree (by
// dst). 4 edges per thread via float4/int4 loads; TPB=512 (halves block
// count / wave transitions; per-lane REDG cost is block-size invariant).
// atomicAdd with unused return -> REDG (no round trip). Floor: spread-REDG
// dispatch at ~1.29 cyc/lane/SM.
// ---------------------------------------------------------------------------
__global__ void __launch_bounds__(512)
scatter_deg_kernel(const float4* __restrict__ w4,
                   const int4*   __restrict__ s4,
                   const int4*   __restrict__ d4,
                   int n4) {
    int tid = blockIdx.x * blockDim.x + threadIdx.x;
    if (tid >= n4) return;
    int4   sv = s4[tid];
    int4   dv = d4[tid];
    float4 wv = w4[tid];
    atomicAdd(&g_norm[sv.x], wv.x);
    atomicAdd(&g_norm[sv.y], wv.y);
    atomicAdd(&g_norm[sv.z], wv.z);
    atomicAdd(&g_norm[sv.w], wv.w);
    atomicAdd(&g_norm[MAX_NODES + dv.x], wv.x);
    atomicAdd(&g_norm[MAX_NODES + dv.y], wv.y);
    atomicAdd(&g_norm[MAX_NODES + dv.z], wv.z);
    atomicAdd(&g_norm[MAX_NODES + dv.w], wv.w);
}

// Scalar tail for generality (launched only when E % 4 != 0).
__global__ void scatter_tail_kernel(const float* __restrict__ w,
                                    const int*   __restrict__ s,
                                    const int*   __restrict__ d,
                                    int start, int E) {
    int i = start + blockIdx.x * blockDim.x + threadIdx.x;
    if (i < E) {
        float wv = w[i];
        atomicAdd(&g_norm[s[i]], wv);
        atomicAdd(&g_norm[MAX_NODES + d[i]], wv);
    }
}

// ---------------------------------------------------------------------------
// Kernel 3: per-node rsqrt, in place, float4-vectorized over the combined
// table. deg==0 -> +inf, but such nodes never appear on the corresponding
// side of any edge, so the inf is never gathered.
// ---------------------------------------------------------------------------
__global__ void rsqrt_deg_kernel() {
    int i = blockIdx.x * blockDim.x + threadIdx.x;
    if (i < (2 * MAX_NODES) / 4) {
        float4 v = ((float4*)g_norm)[i];
        v.x = rsqrtf(v.x);
        v.y = rsqrtf(v.y);
        v.z = rsqrtf(v.z);
        v.w = rsqrtf(v.w);
        ((float4*)g_norm)[i] = v;
    }
}

// ---------------------------------------------------------------------------
// Kernel 4: per-edge gather-multiply. PROTECTED R3/R5 winner (174.5us):
// 4 edges per thread, TPB=256, indices loaded first, 8 random gathers
// front-batched. L1tex-wavefront bound at ~90% of peak (architectural floor).
// ---------------------------------------------------------------------------
__global__ void __launch_bounds__(256)
gather_mul_kernel(const float4* __restrict__ w4,
                  const int4*   __restrict__ s4,
                  const int4*   __restrict__ d4,
                  float4* __restrict__ out4,
                  int n4) {
    int tid = blockIdx.x * blockDim.x + threadIdx.x;
    if (tid >= n4) return;
    int4   sv = s4[tid];
    int4   dv = d4[tid];
    float4 wv = w4[tid];
    // Front-batch all 8 random gathers for deep MLP.
    float sx = g_norm[sv.x], sy = g_norm[sv.y];
    float sz = g_norm[sv.z], sw = g_norm[sv.w];
    float dx = g_norm[MAX_NODES + dv.x], dy = g_norm[MAX_NODES + dv.y];
    float dz = g_norm[MAX_NODES + dv.z], dw = g_norm[MAX_NODES + dv.w];
    float4 r;
    r.x = sx * dx * wv.x;
    r.y = sy * dy * wv.y;
    r.z = sz * dz * wv.z;
    r.w = sw * dw * wv.w;
    out4[tid] = r;
}

// Scalar tail for generality (launched only when E % 4 != 0).
__global__ void gather_tail_kernel(const float* __restrict__ w,
                                   const int*   __restrict__ s,
                                   const int*   __restrict__ d,
                                   float* __restrict__ out,
                                   int start, int E) {
    int i = start + blockIdx.x * blockDim.x + threadIdx.x;
    if (i < E) {
        out[i] = g_norm[s[i]] * g_norm[MAX_NODES + d[i]] * w[i];
    }
}

extern "C" void kernel_launch(void* const* d_in, const int* in_sizes, int n_in,
                              void* d_out, int out_size) {
    const float* w   = (const float*)d_in[0];
    const int*   src = (const int*)d_in[1];
    const int*   dst = (const int*)d_in[2];
    float* out = (float*)d_out;

    int E    = in_sizes[0];
    int n4   = E / 4;
    int tail = E - 4 * n4;

    const int TPB = 256;
    const int SC_TPB = 512;
    const int NV4 = (2 * MAX_NODES) / 4;  // 100,000 float4s

    zero_deg_kernel<<<(NV4 + TPB - 1) / TPB, TPB>>>();

    scatter_deg_kernel<<<(n4 + SC_TPB - 1) / SC_TPB, SC_TPB>>>(
        (const float4*)w, (const int4*)src, (const int4*)dst, n4);
    if (tail > 0) {
        scatter_tail_kernel<<<1, TPB>>>(w, src, dst, 4 * n4, E);
    }

    rsqrt_deg_kernel<<<(NV4 + TPB - 1) / TPB, TPB>>>();

    gather_mul_kernel<<<(n4 + TPB - 1) / TPB, TPB>>>(
        (const float4*)w, (const int4*)src, (const int4*)dst,
        (float4*)out, n4);
    if (tail > 0) {
        gather_tail_kernel<<<1, TPB>>>(w, src, dst, out, 4 * n4, E);
    }
}